// round 1
// baseline (speedup 1.0000x reference)
#include <cuda_runtime.h>
#include <cuda_bf16.h>
#include <cstdint>

// Problem: out[b,f,m] = floor(log2( sum_h (x[b,f,h,0]+1)^2 * fb[m,h] )), h<257
// GEMM view: M = 65536 rows, K = 257, N = 64 mels. fp32, f32x2-packed FMAs.

#define ROWS_TOTAL   65536
#define KREAL        257
#define KP           272          // padded K (mult of 4), filter zero-padded
#define NMELS        64
#define ROW_STRIDE_X 512          // x row has 512 floats, we use first 257

#define TPB          256
#define ROWS_PER_CTA 64
#define CHUNK        68           // K chunk (17 x 16B)
#define NCHUNK       4            // 4*68 = 272
#define KPA          76           // smem mag row stride (pad to break bank conflicts)
#define ABUF         (ROWS_PER_CTA * KPA)   // floats per mag buffer
#define WSIZE        (NMELS * KP)           // floats for filter
#define SMEM_FLOATS  (WSIZE + 2 * ABUF)
#define F4_PER_CHUNK (ROWS_PER_CTA * 17)    // 1088 float4 per chunk
#define NLOAD        5                      // ceil(1088/256)

typedef unsigned long long ull;

__device__ __forceinline__ ull fma2(ull a, ull b, ull c) {
    ull d;
    asm("fma.rn.f32x2 %0, %1, %2, %3;" : "=l"(d) : "l"(a), "l"(b), "l"(c));
    return d;
}

__device__ __forceinline__ void ldg_chunk(const float* __restrict__ x,
                                          size_t rowBase, int k0, int tid,
                                          float4* st) {
#pragma unroll
    for (int p = 0; p < NLOAD; ++p) {
        int idx = tid + p * TPB;
        if (idx < F4_PER_CHUNK) {
            int row = idx / 17;
            int c   = idx % 17;
            st[p] = *reinterpret_cast<const float4*>(
                x + (rowBase + (size_t)row) * ROW_STRIDE_X + k0 + c * 4);
        }
    }
}

__device__ __forceinline__ void sts_chunk(float* sAbuf, int tid, const float4* st) {
#pragma unroll
    for (int p = 0; p < NLOAD; ++p) {
        int idx = tid + p * TPB;
        if (idx < F4_PER_CHUNK) {
            int row = idx / 17;
            int c   = idx % 17;
            float4 v = st[p];
            float ax = v.x + 1.0f, ay = v.y + 1.0f, az = v.z + 1.0f, aw = v.w + 1.0f;
            float4 m;
            m.x = ax * ax; m.y = ay * ay; m.z = az * az; m.w = aw * aw;
            *reinterpret_cast<float4*>(sAbuf + row * KPA + c * 4) = m;
        }
    }
}

__global__ void __launch_bounds__(TPB, 2)
lmfe_kernel(const float* __restrict__ x,
            const float* __restrict__ fb,
            float* __restrict__ out) {
    extern __shared__ float smem[];
    float* sW = smem;               // [64][272], 16B-chunk swizzled per mel
    float* sA = smem + WSIZE;       // [2][64][76]

    const int tid = threadIdx.x;
    const size_t rowBase = (size_t)blockIdx.x * ROWS_PER_CTA;

    // ---- load filter into smem (swizzled, zero-padded to KP) ----
    for (int idx = tid; idx < WSIZE; idx += TPB) {
        int m = idx / KP;
        int k = idx - m * KP;
        float v = (k < KREAL) ? fb[m * KREAL + k] : 0.0f;
        int c   = k >> 2;
        int csw = (c < 64) ? (c ^ ((m >> 2) & 7)) : c;
        sW[m * KP + (csw << 2) + (k & 3)] = v;
    }

    // ---- stage chunk 0 ----
    float4 st[NLOAD];
    ldg_chunk(x, rowBase, 0, tid, st);
    sts_chunk(sA, tid, st);
    __syncthreads();   // filter + chunk0 visible

    const int mg = tid & 15;        // mel group  -> mels m0..m0+3
    const int rg = tid >> 4;        // row group  -> rows r0..r0+3
    const int m0 = mg * 4;
    const int r0 = rg * 4;
    const int swz = mg & 7;
    const float* wRow0 = sW + m0 * KP;

    ull acc[4][4];
#pragma unroll
    for (int j = 0; j < 4; ++j)
#pragma unroll
        for (int i = 0; i < 4; ++i) acc[j][i] = 0ull;

    for (int ch = 0; ch < NCHUNK; ++ch) {
        if (ch < NCHUNK - 1)
            ldg_chunk(x, rowBase, (ch + 1) * CHUNK, tid, st);

        const float* aBuf = sA + (ch & 1) * ABUF;
        const int cBase = ch * 17;

#pragma unroll 1
        for (int t = 0; t < 17; ++t) {
            const int cc  = cBase + t;
            const int csw = (cc < 64) ? (cc ^ swz) : cc;

            ulonglong2 w[4];
#pragma unroll
            for (int i = 0; i < 4; ++i)
                w[i] = *reinterpret_cast<const ulonglong2*>(wRow0 + i * KP + csw * 4);

            ulonglong2 a[4];
#pragma unroll
            for (int j = 0; j < 4; ++j)
                a[j] = *reinterpret_cast<const ulonglong2*>(aBuf + (r0 + j) * KPA + t * 4);

#pragma unroll
            for (int j = 0; j < 4; ++j)
#pragma unroll
                for (int i = 0; i < 4; ++i) {
                    acc[j][i] = fma2(a[j].x, w[i].x, acc[j][i]);
                    acc[j][i] = fma2(a[j].y, w[i].y, acc[j][i]);
                }
        }

        if (ch < NCHUNK - 1)
            sts_chunk(sA + ((ch + 1) & 1) * ABUF, tid, st);
        __syncthreads();
    }

    // ---- epilogue: v = lo+hi, out = floor(log2(v)) ----
#pragma unroll
    for (int j = 0; j < 4; ++j) {
        float4 o;
        float vals[4];
#pragma unroll
        for (int i = 0; i < 4; ++i) {
            float2 f = *reinterpret_cast<float2*>(&acc[j][i]);
            float v = f.x + f.y;
            vals[i] = floorf(log2f(v));
        }
        o.x = vals[0]; o.y = vals[1]; o.z = vals[2]; o.w = vals[3];
        *reinterpret_cast<float4*>(
            out + (rowBase + (size_t)(r0 + j)) * NMELS + m0) = o;
    }
}

extern "C" void kernel_launch(void* const* d_in, const int* in_sizes, int n_in,
                              void* d_out, int out_size) {
    const float* x  = (const float*)d_in[0];   // (256,256,512,1) fp32
    const float* fb = (const float*)d_in[1];   // (64,257) fp32
    float* out = (float*)d_out;                // (256,256,64,1) fp32

    const int smemBytes = SMEM_FLOATS * 4;     // 108,544 B
    cudaFuncSetAttribute(lmfe_kernel,
                         cudaFuncAttributeMaxDynamicSharedMemorySize, smemBytes);

    dim3 grid(ROWS_TOTAL / ROWS_PER_CTA);      // 1024
    lmfe_kernel<<<grid, TPB, smemBytes>>>(x, fb, out);
}

// round 2
// speedup vs baseline: 1.0613x; 1.0613x over previous
#include <cuda_runtime.h>
#include <cuda_bf16.h>
#include <cstdint>

// out[b,f,m] = floor(log2( sum_h (x[b,f,h,0]+1)^2 * fb[m,h] )), h<257
// GEMM view: M = 65536 rows, K = 257 (pad 272), N = 64 mels. f32x2-packed FMAs.

#define ROWS_TOTAL   65536
#define KREAL        257
#define KP           272          // padded K, filter zero-padded
#define NMELS        64
#define ROW_STRIDE_X 512

#define TPB          256
#define ROWS_PER_CTA 64
#define CHUNK        68           // 17 x 16B
#define NCHUNK       4            // 4*68 = 272
#define KPA          76           // mag row stride (76 mod 32 = 12 -> conflict-free)
#define ABUF         (ROWS_PER_CTA * KPA)
#define WSIZE        (NMELS * KP)
#define SMEM_FLOATS  (WSIZE + 2 * ABUF)
#define F4_PER_CHUNK (ROWS_PER_CTA * 17)    // 1088
#define NLOAD        5

typedef unsigned long long ull;

__device__ __forceinline__ ull fma2(ull a, ull b, ull c) {
    ull d;
    asm("fma.rn.f32x2 %0, %1, %2, %3;" : "=l"(d) : "l"(a), "l"(b), "l"(c));
    return d;
}

__device__ __forceinline__ void ldg_chunk(const float* __restrict__ x,
                                          size_t rowBase, int k0, int tid,
                                          float4* st) {
#pragma unroll
    for (int p = 0; p < NLOAD; ++p) {
        int idx = tid + p * TPB;
        if (idx < F4_PER_CHUNK) {
            int row = idx / 17;
            int c   = idx % 17;
            st[p] = *reinterpret_cast<const float4*>(
                x + (rowBase + (size_t)row) * ROW_STRIDE_X + k0 + c * 4);
        }
    }
}

__device__ __forceinline__ void sts_chunk(float* sAbuf, int tid, const float4* st) {
#pragma unroll
    for (int p = 0; p < NLOAD; ++p) {
        int idx = tid + p * TPB;
        if (idx < F4_PER_CHUNK) {
            int row = idx / 17;
            int c   = idx % 17;
            float4 v = st[p];
            float ax = v.x + 1.0f, ay = v.y + 1.0f, az = v.z + 1.0f, aw = v.w + 1.0f;
            float4 m;
            m.x = ax * ax; m.y = ay * ay; m.z = az * az; m.w = aw * aw;
            *reinterpret_cast<float4*>(sAbuf + row * KPA + c * 4) = m;
        }
    }
}

__global__ void __launch_bounds__(TPB, 2)
lmfe_kernel(const float* __restrict__ x,
            const float* __restrict__ fb,
            float* __restrict__ out) {
    extern __shared__ float smem[];
    float* sW = smem;               // [64][272], 16B-chunk swizzled per mel
    float* sA = smem + WSIZE;       // [2][64][76]

    const int tid = threadIdx.x;
    const size_t rowBase = (size_t)blockIdx.x * ROWS_PER_CTA;

    // ---- filter into smem (chunk-swizzled by (m>>2)&7, zero-padded) ----
    for (int idx = tid; idx < WSIZE; idx += TPB) {
        int m = idx / KP;
        int k = idx - m * KP;
        float v = (k < KREAL) ? fb[m * KREAL + k] : 0.0f;
        int c   = k >> 2;
        int csw = (c < 64) ? (c ^ ((m >> 2) & 7)) : c;
        sW[m * KP + (csw << 2) + (k & 3)] = v;
    }

    // ---- stage chunk 0 ----
    float4 st[NLOAD];
    ldg_chunk(x, rowBase, 0, tid, st);
    sts_chunk(sA, tid, st);
    __syncthreads();

    // Lane map: 8 row-groups x 4 mel-groups per warp.
    // w-loads: 4 distinct 16B addrs (8-way bcast, XOR-swizzle -> 1 wavefront)
    // a-loads: 8 distinct 16B addrs at stride 76 words (12 mod 32) -> 1 wavefront
    const int lane    = tid & 31;
    const int warp    = tid >> 5;
    const int mg      = lane & 3;
    const int rg      = lane >> 2;
    const int warpMel = warp & 3;
    const int warpRow = warp >> 2;
    const int m0      = warpMel * 16 + mg * 4;
    const int rBase   = warpRow * 32 + rg;    // thread rows: rBase + 8*j
    const int swz     = (m0 >> 2) & 7;
    const float* wRow0 = sW + m0 * KP;

    ull acc[4][4];
#pragma unroll
    for (int j = 0; j < 4; ++j)
#pragma unroll
        for (int i = 0; i < 4; ++i) acc[j][i] = 0ull;

    for (int ch = 0; ch < NCHUNK; ++ch) {
        if (ch < NCHUNK - 1)
            ldg_chunk(x, rowBase, (ch + 1) * CHUNK, tid, st);

        const float* aBuf = sA + (ch & 1) * ABUF;
        const int cBase = ch * 17;

#pragma unroll 1
        for (int t = 0; t < 17; ++t) {
            const int cc  = cBase + t;
            const int csw = (cc < 64) ? (cc ^ swz) : cc;

            ulonglong2 w[4];
#pragma unroll
            for (int i = 0; i < 4; ++i)
                w[i] = *reinterpret_cast<const ulonglong2*>(wRow0 + i * KP + csw * 4);

            ulonglong2 a[4];
#pragma unroll
            for (int j = 0; j < 4; ++j)
                a[j] = *reinterpret_cast<const ulonglong2*>(
                    aBuf + (rBase + 8 * j) * KPA + t * 4);

#pragma unroll
            for (int j = 0; j < 4; ++j)
#pragma unroll
                for (int i = 0; i < 4; ++i) {
                    acc[j][i] = fma2(a[j].x, w[i].x, acc[j][i]);
                    acc[j][i] = fma2(a[j].y, w[i].y, acc[j][i]);
                }
        }

        if (ch < NCHUNK - 1)
            sts_chunk(sA + ((ch + 1) & 1) * ABUF, tid, st);
        __syncthreads();
    }

    // ---- epilogue: v = lo+hi, out = floor(log2(v)) ----
#pragma unroll
    for (int j = 0; j < 4; ++j) {
        float4 o;
        float vals[4];
#pragma unroll
        for (int i = 0; i < 4; ++i) {
            float2 f = *reinterpret_cast<float2*>(&acc[j][i]);
            float v = f.x + f.y;
            vals[i] = floorf(log2f(v));
        }
        o.x = vals[0]; o.y = vals[1]; o.z = vals[2]; o.w = vals[3];
        *reinterpret_cast<float4*>(
            out + (rowBase + (size_t)(rBase + 8 * j)) * NMELS + m0) = o;
    }
}

extern "C" void kernel_launch(void* const* d_in, const int* in_sizes, int n_in,
                              void* d_out, int out_size) {
    const float* x  = (const float*)d_in[0];   // (256,256,512,1) fp32
    const float* fb = (const float*)d_in[1];   // (64,257) fp32
    float* out = (float*)d_out;                // (256,256,64,1) fp32

    const int smemBytes = SMEM_FLOATS * 4;     // 108,544 B
    cudaFuncSetAttribute(lmfe_kernel,
                         cudaFuncAttributeMaxDynamicSharedMemorySize, smemBytes);

    dim3 grid(ROWS_TOTAL / ROWS_PER_CTA);      // 1024
    lmfe_kernel<<<grid, TPB, smemBytes>>>(x, fb, out);
}